// round 1
// baseline (speedup 1.0000x reference)
#include <cuda_runtime.h>

// GMEdgeConv: two edge-MLP branches with segment-max pooling + final GEMM.
//   branch(x, ei): e = [x[i], x[j]-x[i]] (128) -> relu(e@W1+b1) (64) -> relu(@W2+b2) (64)
//                  pooled[n] = max over edges with i==n (>=0, empty rows -> 0)
//   out = relu([topo, geo] @ Wf + bf)   [N, 64] fp32
//
// Design: persistent blocks, 128-edge tiles, shared-mem GEMM with 8x4 register
// tiles (FFMA-bound). Segment max via int-bitpattern atomicMax on nonneg floats,
// filtered by a plain L2 read (safe: pooled is monotone non-decreasing).

#define N_MAX 100000
#define TILE_E 128

__device__ float g_pool[2][(size_t)N_MAX * 64];

__global__ __launch_bounds__(256, 1)
void branch_kernel(const float* __restrict__ x,
                   const int* __restrict__ ei_t, const int* __restrict__ ei_g,
                   const float* __restrict__ Wt1, const float* __restrict__ bt1,
                   const float* __restrict__ Wt2, const float* __restrict__ bt2,
                   const float* __restrict__ Wg1, const float* __restrict__ bg1,
                   const float* __restrict__ Wg2, const float* __restrict__ bg2,
                   int nE, int nTiles)
{
    extern __shared__ float sm[];
    float* W1s = sm;                    // 128*64
    float* W2s = W1s + 128 * 64;        // 64*64
    float* b1s = W2s + 64 * 64;         // 64
    float* b2s = b1s + 64;              // 64
    float* At  = b2s + 64;              // 64 x 132 (k-major edge tile)
    float* Hs  = At + 64 * 132;         // 128 x 68 (edge-major h1 tile)
    int*   eis = (int*)(Hs + 128 * 68); // 128
    int*   ejs = eis + TILE_E;          // 128

    const int tid = threadIdx.x;
    const int tx  = tid & 15;   // column group: cols 4*tx .. 4*tx+3
    const int ty  = tid >> 4;   // edge group:   edges 8*ty .. 8*ty+7
    const int br  = blockIdx.y;

    const int*   ei = br ? ei_g : ei_t;
    const float* W1 = br ? Wg1 : Wt1;
    const float* b1 = br ? bg1 : bt1;
    const float* W2 = br ? Wg2 : Wt2;
    const float* b2 = br ? bg2 : bt2;
    float* pool = g_pool[br];

    // Stage weights once per (persistent) block.
    for (int idx = tid; idx < 128 * 64; idx += 256) W1s[idx] = W1[idx];
    for (int idx = tid; idx < 64 * 64;  idx += 256) W2s[idx] = W2[idx];
    if (tid < 64) { b1s[tid] = b1[tid]; b2s[tid] = b2[tid]; }

    for (int tile = blockIdx.x; tile < nTiles; tile += gridDim.x) {
        const int ebase = tile * TILE_E;

        __syncthreads();  // protects weight staging (1st iter) + eis/ejs reuse
        if (tid < TILE_E) {
            int e = ebase + tid;
            eis[tid] = (e < nE) ? ei[e] : -1;
            ejs[tid] = (e < nE) ? ei[nE + e] : -1;
        }
        __syncthreads();

        float acc[8][4];
        #pragma unroll
        for (int ii = 0; ii < 8; ii++)
            #pragma unroll
            for (int j = 0; j < 4; j++) acc[ii][j] = 0.f;

        // ---- build A half 0: A[k][e] = x[i_e][k], k = 0..63 ----
        #pragma unroll
        for (int e = ty; e < TILE_E; e += 16) {
            int ni = eis[e];
            float4 v = make_float4(0.f, 0.f, 0.f, 0.f);
            if (ni >= 0) v = *(const float4*)(x + (size_t)ni * 64 + 4 * tx);
            At[(4 * tx + 0) * 132 + e] = v.x;
            At[(4 * tx + 1) * 132 + e] = v.y;
            At[(4 * tx + 2) * 132 + e] = v.z;
            At[(4 * tx + 3) * 132 + e] = v.w;
        }
        __syncthreads();

        // ---- GEMM1, k = 0..63 (W1 rows 0..63) ----
        #pragma unroll 8
        for (int k = 0; k < 64; k++) {
            float4 w  = *(const float4*)(W1s + k * 64 + 4 * tx);
            float4 a0 = *(const float4*)(At + k * 132 + 8 * ty);
            float4 a1 = *(const float4*)(At + k * 132 + 8 * ty + 4);
            float a[8] = {a0.x, a0.y, a0.z, a0.w, a1.x, a1.y, a1.z, a1.w};
            #pragma unroll
            for (int ii = 0; ii < 8; ii++) {
                acc[ii][0] += a[ii] * w.x;
                acc[ii][1] += a[ii] * w.y;
                acc[ii][2] += a[ii] * w.z;
                acc[ii][3] += a[ii] * w.w;
            }
        }
        __syncthreads();

        // ---- build A half 1: A[k][e] = x[j_e][k] - x[i_e][k] ----
        #pragma unroll
        for (int e = ty; e < TILE_E; e += 16) {
            int ni = eis[e], nj = ejs[e];
            float4 d = make_float4(0.f, 0.f, 0.f, 0.f);
            if (ni >= 0) {
                float4 vi = *(const float4*)(x + (size_t)ni * 64 + 4 * tx);
                float4 vj = *(const float4*)(x + (size_t)nj * 64 + 4 * tx);
                d = make_float4(vj.x - vi.x, vj.y - vi.y, vj.z - vi.z, vj.w - vi.w);
            }
            At[(4 * tx + 0) * 132 + e] = d.x;
            At[(4 * tx + 1) * 132 + e] = d.y;
            At[(4 * tx + 2) * 132 + e] = d.z;
            At[(4 * tx + 3) * 132 + e] = d.w;
        }
        __syncthreads();

        // ---- GEMM1, k = 64..127 (W1 rows 64..127) ----
        #pragma unroll 8
        for (int k = 0; k < 64; k++) {
            float4 w  = *(const float4*)(W1s + (64 + k) * 64 + 4 * tx);
            float4 a0 = *(const float4*)(At + k * 132 + 8 * ty);
            float4 a1 = *(const float4*)(At + k * 132 + 8 * ty + 4);
            float a[8] = {a0.x, a0.y, a0.z, a0.w, a1.x, a1.y, a1.z, a1.w};
            #pragma unroll
            for (int ii = 0; ii < 8; ii++) {
                acc[ii][0] += a[ii] * w.x;
                acc[ii][1] += a[ii] * w.y;
                acc[ii][2] += a[ii] * w.z;
                acc[ii][3] += a[ii] * w.w;
            }
        }

        // ---- epilogue 1: h1 = relu(acc + b1) -> Hs (edge-major) ----
        {
            float bb0 = b1s[4 * tx + 0], bb1 = b1s[4 * tx + 1];
            float bb2 = b1s[4 * tx + 2], bb3 = b1s[4 * tx + 3];
            #pragma unroll
            for (int ii = 0; ii < 8; ii++) {
                int e = 8 * ty + ii;
                float4 hv;
                hv.x = fmaxf(acc[ii][0] + bb0, 0.f);
                hv.y = fmaxf(acc[ii][1] + bb1, 0.f);
                hv.z = fmaxf(acc[ii][2] + bb2, 0.f);
                hv.w = fmaxf(acc[ii][3] + bb3, 0.f);
                *(float4*)(Hs + e * 68 + 4 * tx) = hv;
            }
        }
        __syncthreads();

        // ---- GEMM2: h2 = h1 @ W2, k = 0..63 ----
        #pragma unroll
        for (int ii = 0; ii < 8; ii++)
            #pragma unroll
            for (int j = 0; j < 4; j++) acc[ii][j] = 0.f;

        #pragma unroll 4
        for (int k = 0; k < 64; k += 4) {
            float4 w0 = *(const float4*)(W2s + (k + 0) * 64 + 4 * tx);
            float4 w1 = *(const float4*)(W2s + (k + 1) * 64 + 4 * tx);
            float4 w2 = *(const float4*)(W2s + (k + 2) * 64 + 4 * tx);
            float4 w3 = *(const float4*)(W2s + (k + 3) * 64 + 4 * tx);
            #pragma unroll
            for (int ii = 0; ii < 8; ii++) {
                float4 a = *(const float4*)(Hs + (8 * ty + ii) * 68 + k);
                acc[ii][0] += a.x * w0.x + a.y * w1.x + a.z * w2.x + a.w * w3.x;
                acc[ii][1] += a.x * w0.y + a.y * w1.y + a.z * w2.y + a.w * w3.y;
                acc[ii][2] += a.x * w0.z + a.y * w1.z + a.z * w2.z + a.w * w3.z;
                acc[ii][3] += a.x * w0.w + a.y * w1.w + a.z * w2.w + a.w * w3.w;
            }
        }

        // ---- epilogue 2: relu + filtered segment-max atomics ----
        {
            float cb0 = b2s[4 * tx + 0], cb1 = b2s[4 * tx + 1];
            float cb2 = b2s[4 * tx + 2], cb3 = b2s[4 * tx + 3];
            #pragma unroll
            for (int ii = 0; ii < 8; ii++) {
                int e = 8 * ty + ii;
                int node = eis[e];
                if (node < 0) continue;
                float* pr = pool + (size_t)node * 64 + 4 * tx;
                float v0 = fmaxf(acc[ii][0] + cb0, 0.f);
                float v1 = fmaxf(acc[ii][1] + cb1, 0.f);
                float v2 = fmaxf(acc[ii][2] + cb2, 0.f);
                float v3 = fmaxf(acc[ii][3] + cb3, 0.f);
                // pooled only grows; a stale read >= v proves final max >= v.
                if (v0 > 0.f && v0 > __ldcg(pr + 0))
                    atomicMax((int*)(pr + 0), __float_as_int(v0));
                if (v1 > 0.f && v1 > __ldcg(pr + 1))
                    atomicMax((int*)(pr + 1), __float_as_int(v1));
                if (v2 > 0.f && v2 > __ldcg(pr + 2))
                    atomicMax((int*)(pr + 2), __float_as_int(v2));
                if (v3 > 0.f && v3 > __ldcg(pr + 3))
                    atomicMax((int*)(pr + 3), __float_as_int(v3));
            }
        }
    }
}

__global__ __launch_bounds__(256, 1)
void final_kernel(const float* __restrict__ Wf, const float* __restrict__ bf,
                  float* __restrict__ out, int nN)
{
    extern __shared__ float sm[];
    float* Wfs = sm;             // 128*64
    float* bfs = Wfs + 128 * 64; // 64
    float* At  = bfs + 64;       // 128 x 132

    const int tid = threadIdx.x;
    const int tx  = tid & 15;
    const int ty  = tid >> 4;

    for (int idx = tid; idx < 128 * 64; idx += 256) Wfs[idx] = Wf[idx];
    if (tid < 64) bfs[tid] = bf[tid];

    const int base = blockIdx.x * 128;

    // build A[k][node]: k 0..63 = topo, 64..127 = geo
    #pragma unroll
    for (int nd = ty; nd < 128; nd += 16) {
        int node = base + nd;
        float4 a = make_float4(0.f, 0.f, 0.f, 0.f);
        float4 b = make_float4(0.f, 0.f, 0.f, 0.f);
        if (node < nN) {
            a = *(const float4*)(g_pool[0] + (size_t)node * 64 + 4 * tx);
            b = *(const float4*)(g_pool[1] + (size_t)node * 64 + 4 * tx);
        }
        At[(4 * tx + 0) * 132 + nd] = a.x;
        At[(4 * tx + 1) * 132 + nd] = a.y;
        At[(4 * tx + 2) * 132 + nd] = a.z;
        At[(4 * tx + 3) * 132 + nd] = a.w;
        At[(64 + 4 * tx + 0) * 132 + nd] = b.x;
        At[(64 + 4 * tx + 1) * 132 + nd] = b.y;
        At[(64 + 4 * tx + 2) * 132 + nd] = b.z;
        At[(64 + 4 * tx + 3) * 132 + nd] = b.w;
    }
    __syncthreads();

    float acc[8][4];
    #pragma unroll
    for (int ii = 0; ii < 8; ii++)
        #pragma unroll
        for (int j = 0; j < 4; j++) acc[ii][j] = 0.f;

    #pragma unroll 8
    for (int k = 0; k < 128; k++) {
        float4 w  = *(const float4*)(Wfs + k * 64 + 4 * tx);
        float4 a0 = *(const float4*)(At + k * 132 + 8 * ty);
        float4 a1 = *(const float4*)(At + k * 132 + 8 * ty + 4);
        float a[8] = {a0.x, a0.y, a0.z, a0.w, a1.x, a1.y, a1.z, a1.w};
        #pragma unroll
        for (int ii = 0; ii < 8; ii++) {
            acc[ii][0] += a[ii] * w.x;
            acc[ii][1] += a[ii] * w.y;
            acc[ii][2] += a[ii] * w.z;
            acc[ii][3] += a[ii] * w.w;
        }
    }

    float bb0 = bfs[4 * tx + 0], bb1 = bfs[4 * tx + 1];
    float bb2 = bfs[4 * tx + 2], bb3 = bfs[4 * tx + 3];
    #pragma unroll
    for (int ii = 0; ii < 8; ii++) {
        int node = base + 8 * ty + ii;
        if (node < nN) {
            float4 o;
            o.x = fmaxf(acc[ii][0] + bb0, 0.f);
            o.y = fmaxf(acc[ii][1] + bb1, 0.f);
            o.z = fmaxf(acc[ii][2] + bb2, 0.f);
            o.w = fmaxf(acc[ii][3] + bb3, 0.f);
            *(float4*)(out + (size_t)node * 64 + 4 * tx) = o;
        }
    }
}

extern "C" void kernel_launch(void* const* d_in, const int* in_sizes, int n_in,
                              void* d_out, int out_size)
{
    const float* x   = (const float*)d_in[0];
    const int*   eit = (const int*)d_in[1];
    const int*   eig = (const int*)d_in[2];
    const float* Wt1 = (const float*)d_in[3];
    const float* bt1 = (const float*)d_in[4];
    const float* Wt2 = (const float*)d_in[5];
    const float* bt2 = (const float*)d_in[6];
    const float* Wg1 = (const float*)d_in[7];
    const float* bg1 = (const float*)d_in[8];
    const float* Wg2 = (const float*)d_in[9];
    const float* bg2 = (const float*)d_in[10];
    const float* Wf  = (const float*)d_in[11];
    const float* bf  = (const float*)d_in[12];
    float* out = (float*)d_out;

    const int nN = in_sizes[0] / 64;
    const int nE = in_sizes[1] / 2;
    const int nTiles = (nE + TILE_E - 1) / TILE_E;

    void* poolPtr = nullptr;
    cudaGetSymbolAddress(&poolPtr, g_pool);
    cudaMemsetAsync(poolPtr, 0, sizeof(float) * 2 * (size_t)N_MAX * 64, 0);

    const int smemB = (128 * 64 + 64 * 64 + 64 + 64 + 64 * 132 + 128 * 68) * 4
                      + 2 * TILE_E * 4;
    cudaFuncSetAttribute(branch_kernel,
                         cudaFuncAttributeMaxDynamicSharedMemorySize, smemB);
    dim3 gridB(148, 2);
    branch_kernel<<<gridB, 256, smemB>>>(x, eit, eig,
                                         Wt1, bt1, Wt2, bt2,
                                         Wg1, bg1, Wg2, bg2,
                                         nE, nTiles);

    const int smemF = (128 * 64 + 64 + 128 * 132) * 4;
    cudaFuncSetAttribute(final_kernel,
                         cudaFuncAttributeMaxDynamicSharedMemorySize, smemF);
    final_kernel<<<(nN + 127) / 128, 256, smemF>>>(Wf, bf, out, nN);
}

// round 2
// speedup vs baseline: 2.6468x; 2.6468x over previous
#include <cuda_runtime.h>

// GMEdgeConv, restructured:
//   Identity: concat[xi, xj-xi] @ W1 = xi@(W1a-W1b) + xj@W1b   (W1a=rows 0..63, W1b=rows 64..127)
//   Stage 1 (node_kernel):  g_UV[n] = [ x@(Wt1a-Wt1b) | x@Wt1b | x@(Wg1a-Wg1b) | x@Wg1b ]  [N,256]
//   Stage 2 (branch_kernel, per branch): per edge h1 = relu(U[i]+V[j]+b1),
//            h2 = relu(h1 @ W2 + b2), pool[n] = max over edges with i==n (filtered atomicMax, >=0)
//   Stage 3 (final_kernel): out = relu([pool_t | pool_g] @ Wf + bf)
//
// branch_kernel: 128-edge tiles, each half-warp (ty group) owns its 8 edges end-to-end:
// no __syncthreads in the loop, only __syncwarp. 50KB smem -> 2 blocks/SM.

#define N_MAX 100000
#define TILE_E 128

__device__ float g_pool[2][(size_t)N_MAX * 64];
__device__ float g_UV[(size_t)N_MAX * 256];

// ---------------------------------------------------------------------------
// Stage 1: node projections. Tile = 128 nodes, 512 threads, K=64, 256 out cols.
// ---------------------------------------------------------------------------
__global__ __launch_bounds__(512, 1)
void node_kernel(const float* __restrict__ x,
                 const float* __restrict__ Wt1, const float* __restrict__ Wg1,
                 int nN)
{
    extern __shared__ float sm[];
    float* Wc = sm;              // 64 x 260 (cols: Ut|Vt|Ug|Vg)
    float* As = Wc + 64 * 260;   // 128 x 68 (node-major x tile)

    const int tid = threadIdx.x;
    const int tx  = tid & 31;    // 4 cols each over 128 (per pass)
    const int ty  = tid >> 5;    // 8 nodes each

    // Build combined weight: Wc[k][c]
    for (int idx = tid; idx < 64 * 256; idx += 512) {
        int k = idx >> 8, c = idx & 255;
        float v;
        if (c < 64)        v = Wt1[k * 64 + c] - Wt1[(64 + k) * 64 + c];
        else if (c < 128)  v = Wt1[(64 + k) * 64 + (c - 64)];
        else if (c < 192)  v = Wg1[k * 64 + (c - 128)] - Wg1[(64 + k) * 64 + (c - 128)];
        else               v = Wg1[(64 + k) * 64 + (c - 192)];
        Wc[k * 260 + c] = v;
    }

    const int base = blockIdx.x * 128;
    for (int idx = tid; idx < 128 * 16; idx += 512) {
        int nd = idx >> 4, q = idx & 15;
        float4 v = make_float4(0.f, 0.f, 0.f, 0.f);
        if (base + nd < nN) v = *(const float4*)(x + (size_t)(base + nd) * 64 + 4 * q);
        *(float4*)(As + nd * 68 + 4 * q) = v;
    }
    __syncthreads();

    #pragma unroll
    for (int p = 0; p < 2; p++) {
        const int c = p * 128 + 4 * tx;
        float acc[8][4];
        #pragma unroll
        for (int ii = 0; ii < 8; ii++)
            #pragma unroll
            for (int j = 0; j < 4; j++) acc[ii][j] = 0.f;

        #pragma unroll 4
        for (int k = 0; k < 64; k += 4) {
            float4 w0 = *(const float4*)(Wc + (k + 0) * 260 + c);
            float4 w1 = *(const float4*)(Wc + (k + 1) * 260 + c);
            float4 w2 = *(const float4*)(Wc + (k + 2) * 260 + c);
            float4 w3 = *(const float4*)(Wc + (k + 3) * 260 + c);
            #pragma unroll
            for (int ii = 0; ii < 8; ii++) {
                float4 a = *(const float4*)(As + (8 * ty + ii) * 68 + k);
                acc[ii][0] += a.x * w0.x + a.y * w1.x + a.z * w2.x + a.w * w3.x;
                acc[ii][1] += a.x * w0.y + a.y * w1.y + a.z * w2.y + a.w * w3.y;
                acc[ii][2] += a.x * w0.z + a.y * w1.z + a.z * w2.z + a.w * w3.z;
                acc[ii][3] += a.x * w0.w + a.y * w1.w + a.z * w2.w + a.w * w3.w;
            }
        }
        #pragma unroll
        for (int ii = 0; ii < 8; ii++) {
            int node = base + 8 * ty + ii;
            if (node < nN) {
                float4 o = make_float4(acc[ii][0], acc[ii][1], acc[ii][2], acc[ii][3]);
                *(float4*)(g_UV + (size_t)node * 256 + c) = o;
            }
        }
    }
}

// ---------------------------------------------------------------------------
// Stage 2: per-edge MLP2 + segment max. grid (148, 2), 2 blocks/SM persistent.
// ---------------------------------------------------------------------------
__global__ __launch_bounds__(256, 2)
void branch_kernel(const int* __restrict__ ei_t, const int* __restrict__ ei_g,
                   const float* __restrict__ Wt2, const float* __restrict__ bt1,
                   const float* __restrict__ bt2,
                   const float* __restrict__ Wg2, const float* __restrict__ bg1,
                   const float* __restrict__ bg2,
                   int nE, int nTiles)
{
    extern __shared__ float sm[];
    float* W2s = sm;             // 64 x 64
    float* Hs  = sm + 64 * 64;   // 128 x 68 (edge-major h1)

    const int tid = threadIdx.x;
    const int tx  = tid & 15;    // cols 4tx..4tx+3
    const int ty  = tid >> 4;    // edges 8ty..8ty+7 (half-warp group)
    const int br  = blockIdx.y;

    const int*   ei = br ? ei_g : ei_t;
    const float* W2 = br ? Wg2 : Wt2;
    const float* b1 = br ? bg1 : bt1;
    const float* b2 = br ? bg2 : bt2;
    float* pool = g_pool[br];

    const float* Ub = g_UV + br * 128 + 4 * tx;       // + i*256
    const float* Vb = g_UV + br * 128 + 64 + 4 * tx;  // + j*256
    const float4 b1v = *(const float4*)(b1 + 4 * tx);
    const float4 b2v = *(const float4*)(b2 + 4 * tx);

    for (int idx = tid; idx < 64 * 64; idx += 256) W2s[idx] = W2[idx];
    __syncthreads();

    float* HsMine = Hs + (8 * ty) * 68;

    for (int tile = blockIdx.x; tile < nTiles; tile += gridDim.x) {
        const int e0 = tile * TILE_E + 8 * ty;

        int iidx[8], jidx[8];
        if (e0 + 8 <= nE) {
            int4 a = *(const int4*)(ei + e0);
            int4 b = *(const int4*)(ei + e0 + 4);
            iidx[0] = a.x; iidx[1] = a.y; iidx[2] = a.z; iidx[3] = a.w;
            iidx[4] = b.x; iidx[5] = b.y; iidx[6] = b.z; iidx[7] = b.w;
            int4 c = *(const int4*)(ei + nE + e0);
            int4 d = *(const int4*)(ei + nE + e0 + 4);
            jidx[0] = c.x; jidx[1] = c.y; jidx[2] = c.z; jidx[3] = c.w;
            jidx[4] = d.x; jidx[5] = d.y; jidx[6] = d.z; jidx[7] = d.w;
        } else {
            #pragma unroll
            for (int ii = 0; ii < 8; ii++) {
                bool ok = (e0 + ii) < nE;
                iidx[ii] = ok ? ei[e0 + ii] : -1;
                jidx[ii] = ok ? ei[nE + e0 + ii] : -1;
            }
        }

        // ---- build h1 = relu(U[i] + V[j] + b1) into my Hs rows ----
        #pragma unroll
        for (int ii = 0; ii < 8; ii++) {
            float4 h = make_float4(0.f, 0.f, 0.f, 0.f);
            int ni = iidx[ii];
            if (ni >= 0) {
                int nj = jidx[ii];
                float4 u = *(const float4*)(Ub + (size_t)ni * 256);
                float4 v = *(const float4*)(Vb + (size_t)nj * 256);
                h.x = fmaxf(u.x + v.x + b1v.x, 0.f);
                h.y = fmaxf(u.y + v.y + b1v.y, 0.f);
                h.z = fmaxf(u.z + v.z + b1v.z, 0.f);
                h.w = fmaxf(u.w + v.w + b1v.w, 0.f);
            }
            *(float4*)(HsMine + ii * 68 + 4 * tx) = h;
        }
        __syncwarp();

        // ---- h2 = h1 @ W2 ----
        float acc[8][4];
        #pragma unroll
        for (int ii = 0; ii < 8; ii++)
            #pragma unroll
            for (int j = 0; j < 4; j++) acc[ii][j] = 0.f;

        #pragma unroll 4
        for (int k = 0; k < 64; k += 4) {
            float4 w0 = *(const float4*)(W2s + (k + 0) * 64 + 4 * tx);
            float4 w1 = *(const float4*)(W2s + (k + 1) * 64 + 4 * tx);
            float4 w2 = *(const float4*)(W2s + (k + 2) * 64 + 4 * tx);
            float4 w3 = *(const float4*)(W2s + (k + 3) * 64 + 4 * tx);
            #pragma unroll
            for (int ii = 0; ii < 8; ii++) {
                float4 a = *(const float4*)(HsMine + ii * 68 + k);
                acc[ii][0] += a.x * w0.x + a.y * w1.x + a.z * w2.x + a.w * w3.x;
                acc[ii][1] += a.x * w0.y + a.y * w1.y + a.z * w2.y + a.w * w3.y;
                acc[ii][2] += a.x * w0.z + a.y * w1.z + a.z * w2.z + a.w * w3.z;
                acc[ii][3] += a.x * w0.w + a.y * w1.w + a.z * w2.w + a.w * w3.w;
            }
        }
        __syncwarp();   // all lanes past Hs reads before next tile's overwrite

        // ---- epilogue: relu + filtered segment-max atomics ----
        #pragma unroll
        for (int ii = 0; ii < 8; ii++) {
            int node = iidx[ii];
            if (node < 0) continue;
            float* pr = pool + (size_t)node * 64 + 4 * tx;
            float v0 = fmaxf(acc[ii][0] + b2v.x, 0.f);
            float v1 = fmaxf(acc[ii][1] + b2v.y, 0.f);
            float v2 = fmaxf(acc[ii][2] + b2v.z, 0.f);
            float v3 = fmaxf(acc[ii][3] + b2v.w, 0.f);
            // pool only grows; stale read >= v proves final max >= v. (safe filter)
            if (v0 > 0.f && v0 > __ldcg(pr + 0))
                atomicMax((int*)(pr + 0), __float_as_int(v0));
            if (v1 > 0.f && v1 > __ldcg(pr + 1))
                atomicMax((int*)(pr + 1), __float_as_int(v1));
            if (v2 > 0.f && v2 > __ldcg(pr + 2))
                atomicMax((int*)(pr + 2), __float_as_int(v2));
            if (v3 > 0.f && v3 > __ldcg(pr + 3))
                atomicMax((int*)(pr + 3), __float_as_int(v3));
        }
    }
}

// ---------------------------------------------------------------------------
// Stage 3: out = relu([pool_t | pool_g] @ Wf + bf). Tile = 128 nodes.
// ---------------------------------------------------------------------------
__global__ __launch_bounds__(256, 1)
void final_kernel(const float* __restrict__ Wf, const float* __restrict__ bf,
                  float* __restrict__ out, int nN)
{
    extern __shared__ float sm[];
    float* Wfs = sm;                // 128 x 64
    float* Ns  = Wfs + 128 * 64;    // 128 x 132 (node-major, topo|geo)

    const int tid = threadIdx.x;
    const int tx  = tid & 15;
    const int ty  = tid >> 4;

    for (int idx = tid; idx < 128 * 64; idx += 256) Wfs[idx] = Wf[idx];
    const float4 bfv = *(const float4*)(bf + 4 * tx);

    const int base = blockIdx.x * 128;
    for (int idx = tid; idx < 128 * 16; idx += 256) {
        int nd = idx >> 4, q = idx & 15;
        float4 a = make_float4(0.f, 0.f, 0.f, 0.f);
        float4 b = make_float4(0.f, 0.f, 0.f, 0.f);
        if (base + nd < nN) {
            a = *(const float4*)(g_pool[0] + (size_t)(base + nd) * 64 + 4 * q);
            b = *(const float4*)(g_pool[1] + (size_t)(base + nd) * 64 + 4 * q);
        }
        *(float4*)(Ns + nd * 132 + 4 * q) = a;
        *(float4*)(Ns + nd * 132 + 64 + 4 * q) = b;
    }
    __syncthreads();

    float acc[8][4];
    #pragma unroll
    for (int ii = 0; ii < 8; ii++)
        #pragma unroll
        for (int j = 0; j < 4; j++) acc[ii][j] = 0.f;

    #pragma unroll 4
    for (int k = 0; k < 128; k += 4) {
        float4 w0 = *(const float4*)(Wfs + (k + 0) * 64 + 4 * tx);
        float4 w1 = *(const float4*)(Wfs + (k + 1) * 64 + 4 * tx);
        float4 w2 = *(const float4*)(Wfs + (k + 2) * 64 + 4 * tx);
        float4 w3 = *(const float4*)(Wfs + (k + 3) * 64 + 4 * tx);
        #pragma unroll
        for (int ii = 0; ii < 8; ii++) {
            float4 a = *(const float4*)(Ns + (8 * ty + ii) * 132 + k);
            acc[ii][0] += a.x * w0.x + a.y * w1.x + a.z * w2.x + a.w * w3.x;
            acc[ii][1] += a.x * w0.y + a.y * w1.y + a.z * w2.y + a.w * w3.y;
            acc[ii][2] += a.x * w0.z + a.y * w1.z + a.z * w2.z + a.w * w3.z;
            acc[ii][3] += a.x * w0.w + a.y * w1.w + a.z * w2.w + a.w * w3.w;
        }
    }

    #pragma unroll
    for (int ii = 0; ii < 8; ii++) {
        int node = base + 8 * ty + ii;
        if (node < nN) {
            float4 o;
            o.x = fmaxf(acc[ii][0] + bfv.x, 0.f);
            o.y = fmaxf(acc[ii][1] + bfv.y, 0.f);
            o.z = fmaxf(acc[ii][2] + bfv.z, 0.f);
            o.w = fmaxf(acc[ii][3] + bfv.w, 0.f);
            *(float4*)(out + (size_t)node * 64 + 4 * tx) = o;
        }
    }
}

// ---------------------------------------------------------------------------
extern "C" void kernel_launch(void* const* d_in, const int* in_sizes, int n_in,
                              void* d_out, int out_size)
{
    const float* x   = (const float*)d_in[0];
    const int*   eit = (const int*)d_in[1];
    const int*   eig = (const int*)d_in[2];
    const float* Wt1 = (const float*)d_in[3];
    const float* bt1 = (const float*)d_in[4];
    const float* Wt2 = (const float*)d_in[5];
    const float* bt2 = (const float*)d_in[6];
    const float* Wg1 = (const float*)d_in[7];
    const float* bg1 = (const float*)d_in[8];
    const float* Wg2 = (const float*)d_in[9];
    const float* bg2 = (const float*)d_in[10];
    const float* Wf  = (const float*)d_in[11];
    const float* bf  = (const float*)d_in[12];
    float* out = (float*)d_out;

    const int nN = in_sizes[0] / 64;
    const int nE = in_sizes[1] / 2;
    const int nTiles = (nE + TILE_E - 1) / TILE_E;

    void* poolPtr = nullptr;
    cudaGetSymbolAddress(&poolPtr, g_pool);
    cudaMemsetAsync(poolPtr, 0, sizeof(float) * 2 * (size_t)N_MAX * 64, 0);

    const int smemN = (64 * 260 + 128 * 68) * 4;
    cudaFuncSetAttribute(node_kernel,
                         cudaFuncAttributeMaxDynamicSharedMemorySize, smemN);
    node_kernel<<<(nN + 127) / 128, 512, smemN>>>(x, Wt1, Wg1, nN);

    const int smemB = (64 * 64 + 128 * 68) * 4;
    cudaFuncSetAttribute(branch_kernel,
                         cudaFuncAttributeMaxDynamicSharedMemorySize, smemB);
    dim3 gridB(148, 2);
    branch_kernel<<<gridB, 256, smemB>>>(eit, eig,
                                         Wt2, bt1, bt2,
                                         Wg2, bg1, bg2,
                                         nE, nTiles);

    const int smemF = (128 * 64 + 128 * 132) * 4;
    cudaFuncSetAttribute(final_kernel,
                         cudaFuncAttributeMaxDynamicSharedMemorySize, smemF);
    final_kernel<<<(nN + 127) / 128, 256, smemF>>>(Wf, bf, out, nN);
}

// round 5
// speedup vs baseline: 3.6792x; 1.3900x over previous
#include <cuda_runtime.h>
#include <cstdint>

// GMEdgeConv with warp-level tf32 tensor-core edge GEMM (mma.sync, sm_100-safe):
//   Stage 1 (node_kernel, fp32): g_UV[n] = [x@(Wt1a-Wt1b) | x@Wt1b + bt1 | x@(Wg1a-Wg1b) | x@Wg1b + bg1]
//   Stage 2 (branch_kernel): per warp, 16-edge chunks:
//       h1 = relu(U[i]+V'[j]) -> SMEM (tf32-rn), D = h1 @ W2 via 64x mma.sync.m16n8k8.tf32,
//       epilogue relu(D + b2) + filtered atomicMax segment pooling. No block syncs in loop.
//   Stage 3 (final_kernel, fp32): out = relu([pool_t|pool_g] @ Wf + bf)

#define N_MAX 100000

__device__ float g_pool[2][(size_t)N_MAX * 64];
__device__ float g_UV[(size_t)N_MAX * 256];

// round fp32 -> tf32 (RN on the 13 dropped bits)
__device__ __forceinline__ uint32_t tf32rn(float f) {
    uint32_t u = __float_as_uint(f);
    return (u + 0x1000u) & 0xFFFFE000u;
}

// D += A(16x8 row) @ B(8x8 col), tf32 in, fp32 accum
__device__ __forceinline__ void mma_tf32(float* c, const uint32_t* a,
                                         uint32_t b0, uint32_t b1) {
    asm volatile(
        "mma.sync.aligned.m16n8k8.row.col.f32.tf32.tf32.f32 "
        "{%0,%1,%2,%3}, {%4,%5,%6,%7}, {%8,%9}, {%0,%1,%2,%3};\n"
        : "+f"(c[0]), "+f"(c[1]), "+f"(c[2]), "+f"(c[3])
        : "r"(a[0]), "r"(a[1]), "r"(a[2]), "r"(a[3]), "r"(b0), "r"(b1));
}

// ---------------------------------------------------------------------------
// Stage 1: node projections (fp32), b1 folded into V columns.
// ---------------------------------------------------------------------------
__global__ __launch_bounds__(512, 1)
void node_kernel(const float* __restrict__ x,
                 const float* __restrict__ Wt1, const float* __restrict__ Wg1,
                 const float* __restrict__ bt1, const float* __restrict__ bg1,
                 int nN)
{
    extern __shared__ float sm[];
    float* Wc = sm;              // 64 x 260 (cols: Ut|Vt|Ug|Vg)
    float* As = Wc + 64 * 260;   // 128 x 68

    const int tid = threadIdx.x;
    const int tx  = tid & 31;
    const int ty  = tid >> 5;

    for (int idx = tid; idx < 64 * 256; idx += 512) {
        int k = idx >> 8, c = idx & 255;
        float v;
        if (c < 64)        v = Wt1[k * 64 + c] - Wt1[(64 + k) * 64 + c];
        else if (c < 128)  v = Wt1[(64 + k) * 64 + (c - 64)];
        else if (c < 192)  v = Wg1[k * 64 + (c - 128)] - Wg1[(64 + k) * 64 + (c - 128)];
        else               v = Wg1[(64 + k) * 64 + (c - 192)];
        Wc[k * 260 + c] = v;
    }

    const int base = blockIdx.x * 128;
    for (int idx = tid; idx < 128 * 16; idx += 512) {
        int nd = idx >> 4, q = idx & 15;
        float4 v = make_float4(0.f, 0.f, 0.f, 0.f);
        if (base + nd < nN) v = *(const float4*)(x + (size_t)(base + nd) * 64 + 4 * q);
        *(float4*)(As + nd * 68 + 4 * q) = v;
    }
    __syncthreads();

    #pragma unroll
    for (int p = 0; p < 2; p++) {
        const int c = p * 128 + 4 * tx;
        float acc[8][4];
        #pragma unroll
        for (int ii = 0; ii < 8; ii++)
            #pragma unroll
            for (int j = 0; j < 4; j++) acc[ii][j] = 0.f;

        #pragma unroll 4
        for (int k = 0; k < 64; k += 4) {
            float4 w0 = *(const float4*)(Wc + (k + 0) * 260 + c);
            float4 w1 = *(const float4*)(Wc + (k + 1) * 260 + c);
            float4 w2 = *(const float4*)(Wc + (k + 2) * 260 + c);
            float4 w3 = *(const float4*)(Wc + (k + 3) * 260 + c);
            #pragma unroll
            for (int ii = 0; ii < 8; ii++) {
                float4 a = *(const float4*)(As + (8 * ty + ii) * 68 + k);
                acc[ii][0] += a.x * w0.x + a.y * w1.x + a.z * w2.x + a.w * w3.x;
                acc[ii][1] += a.x * w0.y + a.y * w1.y + a.z * w2.y + a.w * w3.y;
                acc[ii][2] += a.x * w0.z + a.y * w1.z + a.z * w2.z + a.w * w3.z;
                acc[ii][3] += a.x * w0.w + a.y * w1.w + a.z * w2.w + a.w * w3.w;
            }
        }
        float4 bv = make_float4(0.f, 0.f, 0.f, 0.f);
        if (4 * tx >= 64) {
            const float* bp = (p ? bg1 : bt1) + (4 * tx - 64);
            bv = *(const float4*)bp;
        }
        #pragma unroll
        for (int ii = 0; ii < 8; ii++) {
            int node = base + 8 * ty + ii;
            if (node < nN) {
                float4 o = make_float4(acc[ii][0] + bv.x, acc[ii][1] + bv.y,
                                       acc[ii][2] + bv.z, acc[ii][3] + bv.w);
                *(float4*)(g_UV + (size_t)node * 256 + c) = o;
            }
        }
    }
}

// ---------------------------------------------------------------------------
// Stage 2: warp-level tf32 MMA edge GEMM + segment max.
// grid (148, 2): y = branch. 2 CTAs/SM, 8 warps/CTA, warp = 16-edge chunk.
// ---------------------------------------------------------------------------
__global__ __launch_bounds__(256, 2)
void branch_kernel(const int* __restrict__ ei_t, const int* __restrict__ ei_g,
                   const float* __restrict__ Wt2, const float* __restrict__ Wg2,
                   const float* __restrict__ bt2, const float* __restrict__ bg2,
                   int nE)
{
    extern __shared__ float smB[];
    float* W2s = smB;               // 64 x 72 (tf32 bits), conflict-free B frags
    float* Hs  = smB + 64 * 72;     // 8 warps x (16 x 68), conflict-free A frags

    const int tid  = threadIdx.x;
    const int warp = tid >> 5;
    const int lane = tid & 31;
    const int qr   = lane & 3;      // threadID_in_group
    const int gp   = lane >> 2;     // groupID
    const int br   = blockIdx.y;

    const int*   ei = br ? ei_g : ei_t;
    const float* W2 = br ? Wg2 : Wt2;
    const float* b2 = br ? bg2 : bt2;
    float* pool = g_pool[br];

    // Stage W2 (k-major [64][64], pad to 72) as tf32 bits.
    for (int idx = tid; idx < 64 * 64; idx += 256) {
        int k = idx >> 6, n = idx & 63;
        W2s[k * 72 + n] = __uint_as_float(tf32rn(W2[idx]));
    }
    __syncthreads();

    uint32_t* Hw = (uint32_t*)(Hs + warp * (16 * 68));
    const uint32_t* W2u = (const uint32_t*)W2s;

    // preload b2 pairs for this thread's fragment columns
    float2 b2v[8];
    #pragma unroll
    for (int nt = 0; nt < 8; nt++)
        b2v[nt] = *(const float2*)(b2 + nt * 8 + qr * 2);

    const int nChunks = (nE + 15) >> 4;
    const int totalWarps = gridDim.x * 8;

    for (int ch = blockIdx.x * 8 + warp; ch < nChunks; ch += totalWarps) {
        const int e0 = ch << 4;

        int iv;  // lanes 0..15: i of edge (lane); lanes 16..31: j of edge (lane-16)
        if (lane < 16) iv = (e0 + lane < nE) ? ei[e0 + lane] : -1;
        else           iv = (e0 + lane - 16 < nE) ? ei[nE + e0 + lane - 16] : 0;

        // ---- gather + h1 = relu(U[i]+V'[j]) -> Hw (tf32 bits) ----
        {
            const int m = lane & 15, half = lane >> 4;   // edge, 32-col half
            int i = __shfl_sync(0xFFFFFFFFu, iv, m);
            int j = __shfl_sync(0xFFFFFFFFu, iv, 16 + m);
            uint32_t* dst = Hw + m * 68 + half * 32;
            if (i >= 0) {
                const float* U = g_UV + (size_t)i * 256 + br * 128 + half * 32;
                const float* V = g_UV + (size_t)j * 256 + br * 128 + 64 + half * 32;
                #pragma unroll
                for (int c = 0; c < 8; c++) {
                    float4 u = *(const float4*)(U + 4 * c);
                    float4 v = *(const float4*)(V + 4 * c);
                    uint4 hv;
                    hv.x = tf32rn(fmaxf(u.x + v.x, 0.f));
                    hv.y = tf32rn(fmaxf(u.y + v.y, 0.f));
                    hv.z = tf32rn(fmaxf(u.z + v.z, 0.f));
                    hv.w = tf32rn(fmaxf(u.w + v.w, 0.f));
                    *(uint4*)(dst + 4 * c) = hv;
                }
            } else {
                #pragma unroll
                for (int c = 0; c < 8; c++)
                    *(uint4*)(dst + 4 * c) = make_uint4(0u, 0u, 0u, 0u);
            }
        }
        __syncwarp();

        // ---- D[16x64] = h1 @ W2 via 8x8 m16n8k8 tf32 MMAs ----
        float acc[8][4];
        #pragma unroll
        for (int nt = 0; nt < 8; nt++)
            #pragma unroll
            for (int q = 0; q < 4; q++) acc[nt][q] = 0.f;

        #pragma unroll
        for (int kt = 0; kt < 8; kt++) {
            uint32_t a[4];
            a[0] = Hw[gp * 68 + kt * 8 + qr];
            a[1] = Hw[(gp + 8) * 68 + kt * 8 + qr];
            a[2] = Hw[gp * 68 + kt * 8 + qr + 4];
            a[3] = Hw[(gp + 8) * 68 + kt * 8 + qr + 4];
            #pragma unroll
            for (int nt = 0; nt < 8; nt++) {
                uint32_t b0 = W2u[(kt * 8 + qr) * 72 + nt * 8 + gp];
                uint32_t b1 = W2u[(kt * 8 + qr + 4) * 72 + nt * 8 + gp];
                mma_tf32(acc[nt], a, b0, b1);
            }
        }
        __syncwarp();   // all A-frag reads done before next chunk's STS

        // ---- epilogue: relu(D + b2), filtered segment-max atomics ----
        int i1 = __shfl_sync(0xFFFFFFFFu, iv, gp);       // edge gp
        int i2 = __shfl_sync(0xFFFFFFFFu, iv, gp + 8);   // edge gp+8
        if (i1 >= 0) {
            float* pr = pool + (size_t)i1 * 64 + qr * 2;
            #pragma unroll
            for (int nt = 0; nt < 8; nt++) {
                float va = fmaxf(acc[nt][0] + b2v[nt].x, 0.f);
                float vb = fmaxf(acc[nt][1] + b2v[nt].y, 0.f);
                float2 cur = __ldcg((const float2*)(pr + nt * 8));
                // pool only grows; stale read >= v proves final max >= v.
                if (va > cur.x) atomicMax((int*)(pr + nt * 8),     __float_as_int(va));
                if (vb > cur.y) atomicMax((int*)(pr + nt * 8 + 1), __float_as_int(vb));
            }
        }
        if (i2 >= 0) {
            float* pr = pool + (size_t)i2 * 64 + qr * 2;
            #pragma unroll
            for (int nt = 0; nt < 8; nt++) {
                float va = fmaxf(acc[nt][2] + b2v[nt].x, 0.f);
                float vb = fmaxf(acc[nt][3] + b2v[nt].y, 0.f);
                float2 cur = __ldcg((const float2*)(pr + nt * 8));
                if (va > cur.x) atomicMax((int*)(pr + nt * 8),     __float_as_int(va));
                if (vb > cur.y) atomicMax((int*)(pr + nt * 8 + 1), __float_as_int(vb));
            }
        }
    }
}

// ---------------------------------------------------------------------------
// Stage 3: out = relu([pool_t | pool_g] @ Wf + bf)   (fp32)
// ---------------------------------------------------------------------------
__global__ __launch_bounds__(256, 1)
void final_kernel(const float* __restrict__ Wf, const float* __restrict__ bf,
                  float* __restrict__ out, int nN)
{
    extern __shared__ float sm[];
    float* Wfs = sm;                // 128 x 64
    float* Ns  = Wfs + 128 * 64;    // 128 x 132

    const int tid = threadIdx.x;
    const int tx  = tid & 15;
    const int ty  = tid >> 4;

    for (int idx = tid; idx < 128 * 64; idx += 256) Wfs[idx] = Wf[idx];
    const float4 bfv = *(const float4*)(bf + 4 * tx);

    const int base = blockIdx.x * 128;
    for (int idx = tid; idx < 128 * 16; idx += 256) {
        int nd = idx >> 4, q = idx & 15;
        float4 a = make_float4(0.f, 0.f, 0.f, 0.f);
        float4 b = make_float4(0.f, 0.f, 0.f, 0.f);
        if (base + nd < nN) {
            a = *(const float4*)(g_pool[0] + (size_t)(base + nd) * 64 + 4 * q);
            b = *(const float4*)(g_pool[1] + (size_t)(base + nd) * 64 + 4 * q);
        }
        *(float4*)(Ns + nd * 132 + 4 * q) = a;
        *(float4*)(Ns + nd * 132 + 64 + 4 * q) = b;
    }
    __syncthreads();

    float acc[8][4];
    #pragma unroll
    for (int ii = 0; ii < 8; ii++)
        #pragma unroll
        for (int j = 0; j < 4; j++) acc[ii][j] = 0.f;

    #pragma unroll 4
    for (int k = 0; k < 128; k += 4) {
        float4 w0 = *(const float4*)(Wfs + (k + 0) * 64 + 4 * tx);
        float4 w1 = *(const float4*)(Wfs + (k + 1) * 64 + 4 * tx);
        float4 w2 = *(const float4*)(Wfs + (k + 2) * 64 + 4 * tx);
        float4 w3 = *(const float4*)(Wfs + (k + 3) * 64 + 4 * tx);
        #pragma unroll
        for (int ii = 0; ii < 8; ii++) {
            float4 a = *(const float4*)(Ns + (8 * ty + ii) * 132 + k);
            acc[ii][0] += a.x * w0.x + a.y * w1.x + a.z * w2.x + a.w * w3.x;
            acc[ii][1] += a.x * w0.y + a.y * w1.y + a.z * w2.y + a.w * w3.y;
            acc[ii][2] += a.x * w0.z + a.y * w1.z + a.z * w2.z + a.w * w3.z;
            acc[ii][3] += a.x * w0.w + a.y * w1.w + a.z * w2.w + a.w * w3.w;
        }
    }

    #pragma unroll
    for (int ii = 0; ii < 8; ii++) {
        int node = base + 8 * ty + ii;
        if (node < nN) {
            float4 o;
            o.x = fmaxf(acc[ii][0] + bfv.x, 0.f);
            o.y = fmaxf(acc[ii][1] + bfv.y, 0.f);
            o.z = fmaxf(acc[ii][2] + bfv.z, 0.f);
            o.w = fmaxf(acc[ii][3] + bfv.w, 0.f);
            *(float4*)(out + (size_t)node * 64 + 4 * tx) = o;
        }
    }
}

// ---------------------------------------------------------------------------
extern "C" void kernel_launch(void* const* d_in, const int* in_sizes, int n_in,
                              void* d_out, int out_size)
{
    const float* x   = (const float*)d_in[0];
    const int*   eit = (const int*)d_in[1];
    const int*   eig = (const int*)d_in[2];
    const float* Wt1 = (const float*)d_in[3];
    const float* bt1 = (const float*)d_in[4];
    const float* Wt2 = (const float*)d_in[5];
    const float* bt2 = (const float*)d_in[6];
    const float* Wg1 = (const float*)d_in[7];
    const float* bg1 = (const float*)d_in[8];
    const float* Wg2 = (const float*)d_in[9];
    const float* bg2 = (const float*)d_in[10];
    const float* Wf  = (const float*)d_in[11];
    const float* bf  = (const float*)d_in[12];
    float* out = (float*)d_out;

    const int nN = in_sizes[0] / 64;
    const int nE = in_sizes[1] / 2;

    void* poolPtr = nullptr;
    cudaGetSymbolAddress(&poolPtr, g_pool);
    cudaMemsetAsync(poolPtr, 0, sizeof(float) * 2 * (size_t)N_MAX * 64, 0);

    const int smemN = (64 * 260 + 128 * 68) * 4;
    cudaFuncSetAttribute(node_kernel,
                         cudaFuncAttributeMaxDynamicSharedMemorySize, smemN);
    node_kernel<<<(nN + 127) / 128, 512, smemN>>>(x, Wt1, Wg1, bt1, bg1, nN);

    const int smemB = (64 * 72 + 8 * 16 * 68) * 4;
    cudaFuncSetAttribute(branch_kernel,
                         cudaFuncAttributeMaxDynamicSharedMemorySize, smemB);
    dim3 gridB(148, 2);
    branch_kernel<<<gridB, 256, smemB>>>(eit, eig, Wt2, Wg2, bt2, bg2, nE);

    const int smemF = (128 * 64 + 128 * 132) * 4;
    cudaFuncSetAttribute(final_kernel,
                         cudaFuncAttributeMaxDynamicSharedMemorySize, smemF);
    final_kernel<<<(nN + 127) / 128, 256, smemF>>>(Wf, bf, out, nN);
}

// round 6
// speedup vs baseline: 5.4552x; 1.4827x over previous
#include <cuda_runtime.h>
#include <cuda_fp16.h>
#include <cstdint>

// GMEdgeConv, fp16-storage + fp16 tensor-core edge GEMM (mma.sync, sm_100-safe):
//   Stage 1 (node_kernel, fp32 math): g_UVh[n] = fp16([x@(Wt1a-Wt1b) | x@Wt1b+bt1 | x@(Wg1a-Wg1b) | x@Wg1b+bg1])
//       (51 MB table -> L2-resident together with the 51 MB pool)
//   Stage 2 (branch_kernel): per warp, 16-edge chunks:
//       h1 = relu(U[i]+V'[j]) in fp16 -> SMEM, D = h1 @ W2 via 32x mma.sync.m16n8k16.f16 (fp32 accum),
//       epilogue relu(D + b2) + filtered atomicMax segment pooling. No block syncs in loop.
//   Stage 3 (final_kernel, fp32): out = relu([pool_t|pool_g] @ Wf + bf)

#define N_MAX 100000

__device__ float  g_pool[2][(size_t)N_MAX * 64];
__device__ __half g_UVh[(size_t)N_MAX * 256];

// D += A(16x16 f16) @ B(16x8 f16), fp32 accum
__device__ __forceinline__ void mma_f16(float* c, const uint32_t* a,
                                        uint32_t b0, uint32_t b1) {
    asm volatile(
        "mma.sync.aligned.m16n8k16.row.col.f32.f16.f16.f32 "
        "{%0,%1,%2,%3}, {%4,%5,%6,%7}, {%8,%9}, {%0,%1,%2,%3};\n"
        : "+f"(c[0]), "+f"(c[1]), "+f"(c[2]), "+f"(c[3])
        : "r"(a[0]), "r"(a[1]), "r"(a[2]), "r"(a[3]), "r"(b0), "r"(b1));
}

// ---------------------------------------------------------------------------
// Stage 1: node projections (fp32 math, fp16 store), b1 folded into V columns.
// ---------------------------------------------------------------------------
__global__ __launch_bounds__(512, 1)
void node_kernel(const float* __restrict__ x,
                 const float* __restrict__ Wt1, const float* __restrict__ Wg1,
                 const float* __restrict__ bt1, const float* __restrict__ bg1,
                 int nN)
{
    extern __shared__ float sm[];
    float* Wc = sm;              // 64 x 260 (cols: Ut|Vt|Ug|Vg)
    float* As = Wc + 64 * 260;   // 128 x 68

    const int tid = threadIdx.x;
    const int tx  = tid & 31;
    const int ty  = tid >> 5;

    for (int idx = tid; idx < 64 * 256; idx += 512) {
        int k = idx >> 8, c = idx & 255;
        float v;
        if (c < 64)        v = Wt1[k * 64 + c] - Wt1[(64 + k) * 64 + c];
        else if (c < 128)  v = Wt1[(64 + k) * 64 + (c - 64)];
        else if (c < 192)  v = Wg1[k * 64 + (c - 128)] - Wg1[(64 + k) * 64 + (c - 128)];
        else               v = Wg1[(64 + k) * 64 + (c - 192)];
        Wc[k * 260 + c] = v;
    }

    const int base = blockIdx.x * 128;
    for (int idx = tid; idx < 128 * 16; idx += 512) {
        int nd = idx >> 4, q = idx & 15;
        float4 v = make_float4(0.f, 0.f, 0.f, 0.f);
        if (base + nd < nN) v = *(const float4*)(x + (size_t)(base + nd) * 64 + 4 * q);
        *(float4*)(As + nd * 68 + 4 * q) = v;
    }
    __syncthreads();

    #pragma unroll
    for (int p = 0; p < 2; p++) {
        const int c = p * 128 + 4 * tx;
        float acc[8][4];
        #pragma unroll
        for (int ii = 0; ii < 8; ii++)
            #pragma unroll
            for (int j = 0; j < 4; j++) acc[ii][j] = 0.f;

        #pragma unroll 4
        for (int k = 0; k < 64; k += 4) {
            float4 w0 = *(const float4*)(Wc + (k + 0) * 260 + c);
            float4 w1 = *(const float4*)(Wc + (k + 1) * 260 + c);
            float4 w2 = *(const float4*)(Wc + (k + 2) * 260 + c);
            float4 w3 = *(const float4*)(Wc + (k + 3) * 260 + c);
            #pragma unroll
            for (int ii = 0; ii < 8; ii++) {
                float4 a = *(const float4*)(As + (8 * ty + ii) * 68 + k);
                acc[ii][0] += a.x * w0.x + a.y * w1.x + a.z * w2.x + a.w * w3.x;
                acc[ii][1] += a.x * w0.y + a.y * w1.y + a.z * w2.y + a.w * w3.y;
                acc[ii][2] += a.x * w0.z + a.y * w1.z + a.z * w2.z + a.w * w3.z;
                acc[ii][3] += a.x * w0.w + a.y * w1.w + a.z * w2.w + a.w * w3.w;
            }
        }
        float4 bv = make_float4(0.f, 0.f, 0.f, 0.f);
        if (4 * tx >= 64) {
            const float* bp = (p ? bg1 : bt1) + (4 * tx - 64);
            bv = *(const float4*)bp;
        }
        #pragma unroll
        for (int ii = 0; ii < 8; ii++) {
            int node = base + 8 * ty + ii;
            if (node < nN) {
                __half2 h0 = __float22half2_rn(make_float2(acc[ii][0] + bv.x,
                                                           acc[ii][1] + bv.y));
                __half2 h1 = __float22half2_rn(make_float2(acc[ii][2] + bv.z,
                                                           acc[ii][3] + bv.w));
                uint2 pk;
                pk.x = *(uint32_t*)&h0;
                pk.y = *(uint32_t*)&h1;
                *(uint2*)(g_UVh + (size_t)node * 256 + c) = pk;
            }
        }
    }
}

// ---------------------------------------------------------------------------
// Stage 2: warp-level fp16 MMA edge GEMM + segment max.
// grid (222, 2): y = branch. 3 CTAs/SM, 8 warps/CTA, warp = 16-edge chunk.
// ---------------------------------------------------------------------------
__global__ __launch_bounds__(256, 3)
void branch_kernel(const int* __restrict__ ei_t, const int* __restrict__ ei_g,
                   const float* __restrict__ Wt2, const float* __restrict__ Wg2,
                   const float* __restrict__ bt2, const float* __restrict__ bg2,
                   int nE)
{
    __shared__ alignas(16) __half W2T[64 * 72];        // [n][k], stride 72
    __shared__ alignas(16) __half Hs[8][16 * 72];      // per-warp h1, stride 72

    const int tid  = threadIdx.x;
    const int warp = tid >> 5;
    const int lane = tid & 31;
    const int qr   = lane & 3;      // threadID_in_group
    const int gp   = lane >> 2;     // groupID
    const int br   = blockIdx.y;

    const int*   ei = br ? ei_g : ei_t;
    const float* W2 = br ? Wg2 : Wt2;
    const float* b2 = br ? bg2 : bt2;
    float* pool = g_pool[br];

    // Stage W2^T: W2 is [k][n] row-major; store W2T[n*72 + k] (fp16).
    for (int idx = tid; idx < 64 * 64; idx += 256) {
        int k = idx >> 6, n = idx & 63;
        W2T[n * 72 + k] = __float2half_rn(W2[idx]);
    }
    __syncthreads();

    uint32_t* Hw32 = (uint32_t*)Hs[warp];              // row stride = 36 words
    const uint32_t* W2T32 = (const uint32_t*)W2T;

    // preload b2 pairs for this thread's fragment columns
    float2 b2v[8];
    #pragma unroll
    for (int nt = 0; nt < 8; nt++)
        b2v[nt] = *(const float2*)(b2 + nt * 8 + qr * 2);

    const __half2 zero2 = __float2half2_rn(0.f);
    const int nChunks = (nE + 15) >> 4;
    const int totalWarps = gridDim.x * 8;

    for (int ch = blockIdx.x * 8 + warp; ch < nChunks; ch += totalWarps) {
        const int e0 = ch << 4;

        int iv;  // lanes 0..15: i of edge (lane); lanes 16..31: j of edge (lane-16)
        if (lane < 16) iv = (e0 + lane < nE) ? ei[e0 + lane] : -1;
        else           iv = (e0 + lane - 16 < nE) ? ei[nE + e0 + lane - 16] : 0;

        // ---- gather + h1 = relu(U[i]+V'[j]) -> Hw (fp16) ----
        {
            const int m = lane & 15, half = lane >> 4;   // edge, 32-col half
            int i = __shfl_sync(0xFFFFFFFFu, iv, m);
            int j = __shfl_sync(0xFFFFFFFFu, iv, 16 + m);
            __half* dst = Hs[warp] + m * 72 + half * 32;
            if (i >= 0) {
                const uint4* U = (const uint4*)(g_UVh + (size_t)i * 256 + br * 128 + half * 32);
                const uint4* V = (const uint4*)(g_UVh + (size_t)j * 256 + br * 128 + 64 + half * 32);
                #pragma unroll
                for (int c = 0; c < 4; c++) {            // 4 x 16B = 64B = 32 halves
                    uint4 uu = U[c], vv = V[c];
                    uint4 hh;
                    const __half2* up = (const __half2*)&uu;
                    const __half2* vp = (const __half2*)&vv;
                    __half2* hp = (__half2*)&hh;
                    #pragma unroll
                    for (int q = 0; q < 4; q++)
                        hp[q] = __hmax2(__hadd2(up[q], vp[q]), zero2);
                    *(uint4*)(dst + c * 8) = hh;
                }
            } else {
                #pragma unroll
                for (int c = 0; c < 4; c++)
                    *(uint4*)(dst + c * 8) = make_uint4(0u, 0u, 0u, 0u);
            }
        }
        __syncwarp();

        // ---- D[16x64] = h1 @ W2 via 4x8 m16n8k16 f16 MMAs ----
        float acc[8][4];
        #pragma unroll
        for (int nt = 0; nt < 8; nt++)
            #pragma unroll
            for (int q = 0; q < 4; q++) acc[nt][q] = 0.f;

        #pragma unroll
        for (int kt = 0; kt < 4; kt++) {
            uint32_t a[4];
            a[0] = Hw32[gp * 36 + kt * 8 + qr];
            a[1] = Hw32[(gp + 8) * 36 + kt * 8 + qr];
            a[2] = Hw32[gp * 36 + kt * 8 + qr + 4];
            a[3] = Hw32[(gp + 8) * 36 + kt * 8 + qr + 4];
            #pragma unroll
            for (int nt = 0; nt < 8; nt++) {
                uint32_t b0 = W2T32[(nt * 8 + gp) * 36 + kt * 8 + qr];
                uint32_t b1 = W2T32[(nt * 8 + gp) * 36 + kt * 8 + qr + 4];
                mma_f16(acc[nt], a, b0, b1);
            }
        }
        __syncwarp();   // all A-frag reads done before next chunk's STS

        // ---- epilogue: relu(D + b2), filtered segment-max atomics ----
        int i1 = __shfl_sync(0xFFFFFFFFu, iv, gp);       // edge gp
        int i2 = __shfl_sync(0xFFFFFFFFu, iv, gp + 8);   // edge gp+8
        if (i1 >= 0) {
            float* pr = pool + (size_t)i1 * 64 + qr * 2;
            #pragma unroll
            for (int nt = 0; nt < 8; nt++) {
                float va = fmaxf(acc[nt][0] + b2v[nt].x, 0.f);
                float vb = fmaxf(acc[nt][1] + b2v[nt].y, 0.f);
                float2 cur = __ldcg((const float2*)(pr + nt * 8));
                // pool only grows; stale read >= v proves final max >= v.
                if (va > cur.x) atomicMax((int*)(pr + nt * 8),     __float_as_int(va));
                if (vb > cur.y) atomicMax((int*)(pr + nt * 8 + 1), __float_as_int(vb));
            }
        }
        if (i2 >= 0) {
            float* pr = pool + (size_t)i2 * 64 + qr * 2;
            #pragma unroll
            for (int nt = 0; nt < 8; nt++) {
                float va = fmaxf(acc[nt][2] + b2v[nt].x, 0.f);
                float vb = fmaxf(acc[nt][3] + b2v[nt].y, 0.f);
                float2 cur = __ldcg((const float2*)(pr + nt * 8));
                if (va > cur.x) atomicMax((int*)(pr + nt * 8),     __float_as_int(va));
                if (vb > cur.y) atomicMax((int*)(pr + nt * 8 + 1), __float_as_int(vb));
            }
        }
    }
}

// ---------------------------------------------------------------------------
// Stage 3: out = relu([pool_t | pool_g] @ Wf + bf)   (fp32)
// ---------------------------------------------------------------------------
__global__ __launch_bounds__(256, 1)
void final_kernel(const float* __restrict__ Wf, const float* __restrict__ bf,
                  float* __restrict__ out, int nN)
{
    extern __shared__ float sm[];
    float* Wfs = sm;                // 128 x 64
    float* Ns  = Wfs + 128 * 64;    // 128 x 132

    const int tid = threadIdx.x;
    const int tx  = tid & 15;
    const int ty  = tid >> 4;

    for (int idx = tid; idx < 128 * 64; idx += 256) Wfs[idx] = Wf[idx];
    const float4 bfv = *(const float4*)(bf + 4 * tx);

    const int base = blockIdx.x * 128;
    for (int idx = tid; idx < 128 * 16; idx += 256) {
        int nd = idx >> 4, q = idx & 15;
        float4 a = make_float4(0.f, 0.f, 0.f, 0.f);
        float4 b = make_float4(0.f, 0.f, 0.f, 0.f);
        if (base + nd < nN) {
            a = *(const float4*)(g_pool[0] + (size_t)(base + nd) * 64 + 4 * q);
            b = *(const float4*)(g_pool[1] + (size_t)(base + nd) * 64 + 4 * q);
        }
        *(float4*)(Ns + nd * 132 + 4 * q) = a;
        *(float4*)(Ns + nd * 132 + 64 + 4 * q) = b;
    }
    __syncthreads();

    float acc[8][4];
    #pragma unroll
    for (int ii = 0; ii < 8; ii++)
        #pragma unroll
        for (int j = 0; j < 4; j++) acc[ii][j] = 0.f;

    #pragma unroll 4
    for (int k = 0; k < 128; k += 4) {
        float4 w0 = *(const float4*)(Wfs + (k + 0) * 64 + 4 * tx);
        float4 w1 = *(const float4*)(Wfs + (k + 1) * 64 + 4 * tx);
        float4 w2 = *(const float4*)(Wfs + (k + 2) * 64 + 4 * tx);
        float4 w3 = *(const float4*)(Wfs + (k + 3) * 64 + 4 * tx);
        #pragma unroll
        for (int ii = 0; ii < 8; ii++) {
            float4 a = *(const float4*)(Ns + (8 * ty + ii) * 132 + k);
            acc[ii][0] += a.x * w0.x + a.y * w1.x + a.z * w2.x + a.w * w3.x;
            acc[ii][1] += a.x * w0.y + a.y * w1.y + a.z * w2.y + a.w * w3.y;
            acc[ii][2] += a.x * w0.z + a.y * w1.z + a.z * w2.z + a.w * w3.z;
            acc[ii][3] += a.x * w0.w + a.y * w1.w + a.z * w2.w + a.w * w3.w;
        }
    }

    #pragma unroll
    for (int ii = 0; ii < 8; ii++) {
        int node = base + 8 * ty + ii;
        if (node < nN) {
            float4 o;
            o.x = fmaxf(acc[ii][0] + bfv.x, 0.f);
            o.y = fmaxf(acc[ii][1] + bfv.y, 0.f);
            o.z = fmaxf(acc[ii][2] + bfv.z, 0.f);
            o.w = fmaxf(acc[ii][3] + bfv.w, 0.f);
            *(float4*)(out + (size_t)node * 64 + 4 * tx) = o;
        }
    }
}

// ---------------------------------------------------------------------------
extern "C" void kernel_launch(void* const* d_in, const int* in_sizes, int n_in,
                              void* d_out, int out_size)
{
    const float* x   = (const float*)d_in[0];
    const int*   eit = (const int*)d_in[1];
    const int*   eig = (const int*)d_in[2];
    const float* Wt1 = (const float*)d_in[3];
    const float* bt1 = (const float*)d_in[4];
    const float* Wt2 = (const float*)d_in[5];
    const float* bt2 = (const float*)d_in[6];
    const float* Wg1 = (const float*)d_in[7];
    const float* bg1 = (const float*)d_in[8];
    const float* Wg2 = (const float*)d_in[9];
    const float* bg2 = (const float*)d_in[10];
    const float* Wf  = (const float*)d_in[11];
    const float* bf  = (const float*)d_in[12];
    float* out = (float*)d_out;

    const int nN = in_sizes[0] / 64;
    const int nE = in_sizes[1] / 2;

    void* poolPtr = nullptr;
    cudaGetSymbolAddress(&poolPtr, g_pool);
    cudaMemsetAsync(poolPtr, 0, sizeof(float) * 2 * (size_t)N_MAX * 64, 0);

    const int smemN = (64 * 260 + 128 * 68) * 4;
    cudaFuncSetAttribute(node_kernel,
                         cudaFuncAttributeMaxDynamicSharedMemorySize, smemN);
    node_kernel<<<(nN + 127) / 128, 512, smemN>>>(x, Wt1, Wg1, bt1, bg1, nN);

    dim3 gridB(222, 2);
    branch_kernel<<<gridB, 256>>>(eit, eig, Wt2, Wg2, bt2, bg2, nE);

    const int smemF = (128 * 64 + 128 * 132) * 4;
    cudaFuncSetAttribute(final_kernel,
                         cudaFuncAttributeMaxDynamicSharedMemorySize, smemF);
    final_kernel<<<(nN + 127) / 128, 256, smemF>>>(Wf, bf, out, nN);
}

// round 7
// speedup vs baseline: 5.6134x; 1.0290x over previous
#include <cuda_runtime.h>
#include <cuda_fp16.h>
#include <cstdint>

// GMEdgeConv, fp16 storage + fp16 mma.sync edge GEMM, line-coalesced gather:
//   Stage 1 (node_kernel, fp32 math): g_UVh[n] = fp16([x@(Wt1a-Wt1b) | x@Wt1b+bt1 | x@(Wg1a-Wg1b) | x@Wg1b+bg1])
//   Stage 2 (branch_kernel): per warp, 16-edge chunks:
//       coalesced 128B-row gather of raw U[i], V'[j] -> SMEM,
//       h1 = relu(U+V') fused into A-fragment build, D = h1 @ W2 via mma.m16n8k16.f16,
//       epilogue relu(D + b2) + zero-skip + filtered atomicMax segment pooling.
//   Stage 3 (final_kernel, fp32): out = relu([pool_t|pool_g] @ Wf + bf)

#define N_MAX 100000

__device__ float  g_pool[2][(size_t)N_MAX * 64];
__device__ __half g_UVh[(size_t)N_MAX * 256];

// D += A(16x16 f16) @ B(16x8 f16), fp32 accum
__device__ __forceinline__ void mma_f16(float* c, const uint32_t* a,
                                        uint32_t b0, uint32_t b1) {
    asm volatile(
        "mma.sync.aligned.m16n8k16.row.col.f32.f16.f16.f32 "
        "{%0,%1,%2,%3}, {%4,%5,%6,%7}, {%8,%9}, {%0,%1,%2,%3};\n"
        : "+f"(c[0]), "+f"(c[1]), "+f"(c[2]), "+f"(c[3])
        : "r"(a[0]), "r"(a[1]), "r"(a[2]), "r"(a[3]), "r"(b0), "r"(b1));
}

__device__ __forceinline__ uint32_t hrelu_add(uint32_t u, uint32_t v) {
    __half2 z = __float2half2_rn(0.f);
    __half2 r = __hmax2(__hadd2(*(__half2*)&u, *(__half2*)&v), z);
    return *(uint32_t*)&r;
}

// ---------------------------------------------------------------------------
// Stage 1: node projections (fp32 math, fp16 store), b1 folded into V columns.
// ---------------------------------------------------------------------------
__global__ __launch_bounds__(512, 1)
void node_kernel(const float* __restrict__ x,
                 const float* __restrict__ Wt1, const float* __restrict__ Wg1,
                 const float* __restrict__ bt1, const float* __restrict__ bg1,
                 int nN)
{
    extern __shared__ float sm[];
    float* Wc = sm;              // 64 x 260 (cols: Ut|Vt|Ug|Vg)
    float* As = Wc + 64 * 260;   // 128 x 68

    const int tid = threadIdx.x;
    const int tx  = tid & 31;
    const int ty  = tid >> 5;

    for (int idx = tid; idx < 64 * 256; idx += 512) {
        int k = idx >> 8, c = idx & 255;
        float v;
        if (c < 64)        v = Wt1[k * 64 + c] - Wt1[(64 + k) * 64 + c];
        else if (c < 128)  v = Wt1[(64 + k) * 64 + (c - 64)];
        else if (c < 192)  v = Wg1[k * 64 + (c - 128)] - Wg1[(64 + k) * 64 + (c - 128)];
        else               v = Wg1[(64 + k) * 64 + (c - 192)];
        Wc[k * 260 + c] = v;
    }

    const int base = blockIdx.x * 128;
    for (int idx = tid; idx < 128 * 16; idx += 512) {
        int nd = idx >> 4, q = idx & 15;
        float4 v = make_float4(0.f, 0.f, 0.f, 0.f);
        if (base + nd < nN) v = *(const float4*)(x + (size_t)(base + nd) * 64 + 4 * q);
        *(float4*)(As + nd * 68 + 4 * q) = v;
    }
    __syncthreads();

    #pragma unroll
    for (int p = 0; p < 2; p++) {
        const int c = p * 128 + 4 * tx;
        float acc[8][4];
        #pragma unroll
        for (int ii = 0; ii < 8; ii++)
            #pragma unroll
            for (int j = 0; j < 4; j++) acc[ii][j] = 0.f;

        #pragma unroll 4
        for (int k = 0; k < 64; k += 4) {
            float4 w0 = *(const float4*)(Wc + (k + 0) * 260 + c);
            float4 w1 = *(const float4*)(Wc + (k + 1) * 260 + c);
            float4 w2 = *(const float4*)(Wc + (k + 2) * 260 + c);
            float4 w3 = *(const float4*)(Wc + (k + 3) * 260 + c);
            #pragma unroll
            for (int ii = 0; ii < 8; ii++) {
                float4 a = *(const float4*)(As + (8 * ty + ii) * 68 + k);
                acc[ii][0] += a.x * w0.x + a.y * w1.x + a.z * w2.x + a.w * w3.x;
                acc[ii][1] += a.x * w0.y + a.y * w1.y + a.z * w2.y + a.w * w3.y;
                acc[ii][2] += a.x * w0.z + a.y * w1.z + a.z * w2.z + a.w * w3.z;
                acc[ii][3] += a.x * w0.w + a.y * w1.w + a.z * w2.w + a.w * w3.w;
            }
        }
        float4 bv = make_float4(0.f, 0.f, 0.f, 0.f);
        if (4 * tx >= 64) {
            const float* bp = (p ? bg1 : bt1) + (4 * tx - 64);
            bv = *(const float4*)bp;
        }
        #pragma unroll
        for (int ii = 0; ii < 8; ii++) {
            int node = base + 8 * ty + ii;
            if (node < nN) {
                __half2 h0 = __float22half2_rn(make_float2(acc[ii][0] + bv.x,
                                                           acc[ii][1] + bv.y));
                __half2 h1 = __float22half2_rn(make_float2(acc[ii][2] + bv.z,
                                                           acc[ii][3] + bv.w));
                uint2 pk;
                pk.x = *(uint32_t*)&h0;
                pk.y = *(uint32_t*)&h1;
                *(uint2*)(g_UVh + (size_t)node * 256 + c) = pk;
            }
        }
    }
}

// ---------------------------------------------------------------------------
// Stage 2: warp-level fp16 MMA edge GEMM + segment max.
// grid (222, 2): y = branch. 3 CTAs/SM, 8 warps/CTA, warp = 16-edge chunk.
// ---------------------------------------------------------------------------
__global__ __launch_bounds__(256, 3)
void branch_kernel(const int* __restrict__ ei_t, const int* __restrict__ ei_g,
                   const float* __restrict__ Wt2, const float* __restrict__ Wg2,
                   const float* __restrict__ bt2, const float* __restrict__ bg2,
                   int nE)
{
    __shared__ alignas(16) __half W2T[64 * 72];        // [n][k], stride 72
    __shared__ alignas(16) __half UVs[8][2][16 * 72];  // [warp][U/V][edge*72]

    const int tid  = threadIdx.x;
    const int warp = tid >> 5;
    const int lane = tid & 31;
    const int qr   = lane & 3;      // threadID_in_group
    const int gp   = lane >> 2;     // groupID
    const int br   = blockIdx.y;

    const int*   ei = br ? ei_g : ei_t;
    const float* W2 = br ? Wg2 : Wt2;
    const float* b2 = br ? bg2 : bt2;
    float* pool = g_pool[br];

    // Stage W2^T: W2 is [k][n] row-major; store W2T[n*72 + k] (fp16).
    for (int idx = tid; idx < 64 * 64; idx += 256) {
        int k = idx >> 6, n = idx & 63;
        W2T[n * 72 + k] = __float2half_rn(W2[idx]);
    }
    __syncthreads();

    uint32_t* Uw = (uint32_t*)UVs[warp][0];            // row stride 36 words
    uint32_t* Vw = (uint32_t*)UVs[warp][1];
    const uint32_t* W2T32 = (const uint32_t*)W2T;

    // preload b2 pairs for this thread's fragment columns
    float2 b2v[8];
    #pragma unroll
    for (int nt = 0; nt < 8; nt++)
        b2v[nt] = *(const float2*)(b2 + nt * 8 + qr * 2);

    const int grow = lane >> 3;     // row-group within each coalesced LDG
    const int qb   = lane & 7;      // 16B chunk within 128B row

    const int nChunks = (nE + 15) >> 4;
    const int totalWarps = gridDim.x * 8;

    for (int ch = blockIdx.x * 8 + warp; ch < nChunks; ch += totalWarps) {
        const int e0 = ch << 4;

        int iv;  // lanes 0..15: i of edge (lane); lanes 16..31: j of edge (lane-16)
        if (lane < 16) iv = (e0 + lane < nE) ? __ldcs(ei + e0 + lane) : -1;
        else           iv = (e0 + lane - 16 < nE) ? __ldcs(ei + nE + e0 + lane - 16) : 0;

        // ---- coalesced gather: raw U rows (seg 0) and V rows (seg 1) ----
        // Each LDG: 4 rows x 8 lanes x 16B = 4 full 128B lines (4 wavefronts).
        #pragma unroll
        for (int seg = 0; seg < 2; seg++) {
            __half* dstS = UVs[warp][seg];
            #pragma unroll
            for (int gg = 0; gg < 4; gg++) {
                int e = gg * 4 + grow;
                int idx = __shfl_sync(0xFFFFFFFFu, iv, e + seg * 16);
                idx = idx < 0 ? 0 : idx;  // invalid edges: row 0 (output unused)
                const uint4* src = (const uint4*)(g_UVh + (size_t)idx * 256
                                                 + br * 128 + seg * 64) + qb;
                uint4 v = *src;
                *(uint4*)(dstS + e * 72 + qb * 8) = v;
            }
        }
        __syncwarp();

        // ---- D[16x64] = relu(U+V) @ W2 via 4x8 m16n8k16 f16 MMAs,
        //      h1 fused into the A-fragment build ----
        float acc[8][4];
        #pragma unroll
        for (int nt = 0; nt < 8; nt++)
            #pragma unroll
            for (int q = 0; q < 4; q++) acc[nt][q] = 0.f;

        #pragma unroll
        for (int kt = 0; kt < 4; kt++) {
            const int c = kt * 8 + qr;
            uint32_t a[4];
            a[0] = hrelu_add(Uw[gp * 36 + c],           Vw[gp * 36 + c]);
            a[1] = hrelu_add(Uw[(gp + 8) * 36 + c],     Vw[(gp + 8) * 36 + c]);
            a[2] = hrelu_add(Uw[gp * 36 + c + 4],       Vw[gp * 36 + c + 4]);
            a[3] = hrelu_add(Uw[(gp + 8) * 36 + c + 4], Vw[(gp + 8) * 36 + c + 4]);
            #pragma unroll
            for (int nt = 0; nt < 8; nt++) {
                uint32_t b0 = W2T32[(nt * 8 + gp) * 36 + kt * 8 + qr];
                uint32_t b1 = W2T32[(nt * 8 + gp) * 36 + kt * 8 + qr + 4];
                mma_f16(acc[nt], a, b0, b1);
            }
        }
        __syncwarp();   // all UVs reads done before next chunk's STS

        // ---- epilogue: relu(D + b2), zero-skip + filtered segment-max ----
        int i1 = __shfl_sync(0xFFFFFFFFu, iv, gp);       // edge gp
        int i2 = __shfl_sync(0xFFFFFFFFu, iv, gp + 8);   // edge gp+8
        if (i1 >= 0) {
            float* pr = pool + (size_t)i1 * 64 + qr * 2;
            #pragma unroll
            for (int nt = 0; nt < 8; nt++) {
                float va = fmaxf(acc[nt][0] + b2v[nt].x, 0.f);
                float vb = fmaxf(acc[nt][1] + b2v[nt].y, 0.f);
                if (va > 0.f || vb > 0.f) {   // pool >= 0: zero never wins
                    float2 cur = __ldcg((const float2*)(pr + nt * 8));
                    // pool only grows; stale read >= v proves final max >= v.
                    if (va > cur.x) atomicMax((int*)(pr + nt * 8),     __float_as_int(va));
                    if (vb > cur.y) atomicMax((int*)(pr + nt * 8 + 1), __float_as_int(vb));
                }
            }
        }
        if (i2 >= 0) {
            float* pr = pool + (size_t)i2 * 64 + qr * 2;
            #pragma unroll
            for (int nt = 0; nt < 8; nt++) {
                float va = fmaxf(acc[nt][2] + b2v[nt].x, 0.f);
                float vb = fmaxf(acc[nt][3] + b2v[nt].y, 0.f);
                if (va > 0.f || vb > 0.f) {
                    float2 cur = __ldcg((const float2*)(pr + nt * 8));
                    if (va > cur.x) atomicMax((int*)(pr + nt * 8),     __float_as_int(va));
                    if (vb > cur.y) atomicMax((int*)(pr + nt * 8 + 1), __float_as_int(vb));
                }
            }
        }
    }
}

// ---------------------------------------------------------------------------
// Stage 3: out = relu([pool_t | pool_g] @ Wf + bf)   (fp32)
// ---------------------------------------------------------------------------
__global__ __launch_bounds__(256, 1)
void final_kernel(const float* __restrict__ Wf, const float* __restrict__ bf,
                  float* __restrict__ out, int nN)
{
    extern __shared__ float sm[];
    float* Wfs = sm;                // 128 x 64
    float* Ns  = Wfs + 128 * 64;    // 128 x 132

    const int tid = threadIdx.x;
    const int tx  = tid & 15;
    const int ty  = tid >> 4;

    for (int idx = tid; idx < 128 * 64; idx += 256) Wfs[idx] = Wf[idx];
    const float4 bfv = *(const float4*)(bf + 4 * tx);

    const int base = blockIdx.x * 128;
    for (int idx = tid; idx < 128 * 16; idx += 256) {
        int nd = idx >> 4, q = idx & 15;
        float4 a = make_float4(0.f, 0.f, 0.f, 0.f);
        float4 b = make_float4(0.f, 0.f, 0.f, 0.f);
        if (base + nd < nN) {
            a = *(const float4*)(g_pool[0] + (size_t)(base + nd) * 64 + 4 * q);
            b = *(const float4*)(g_pool[1] + (size_t)(base + nd) * 64 + 4 * q);
        }
        *(float4*)(Ns + nd * 132 + 4 * q) = a;
        *(float4*)(Ns + nd * 132 + 64 + 4 * q) = b;
    }
    __syncthreads();

    float acc[8][4];
    #pragma unroll
    for (int ii = 0; ii < 8; ii++)
        #pragma unroll
        for (int j = 0; j < 4; j++) acc[ii][j] = 0.f;

    #pragma unroll 4
    for (int k = 0; k < 128; k += 4) {
        float4 w0 = *(const float4*)(Wfs + (k + 0) * 64 + 4 * tx);
        float4 w1 = *(const float4*)(Wfs + (k + 1) * 64 + 4 * tx);
        float4 w2 = *(const float4*)(Wfs + (k + 2) * 64 + 4 * tx);
        float4 w3 = *(const float4*)(Wfs + (k + 3) * 64 + 4 * tx);
        #pragma unroll
        for (int ii = 0; ii < 8; ii++) {
            float4 a = *(const float4*)(Ns + (8 * ty + ii) * 132 + k);
            acc[ii][0] += a.x * w0.x + a.y * w1.x + a.z * w2.x + a.w * w3.x;
            acc[ii][1] += a.x * w0.y + a.y * w1.y + a.z * w2.y + a.w * w3.y;
            acc[ii][2] += a.x * w0.z + a.y * w1.z + a.z * w2.z + a.w * w3.z;
            acc[ii][3] += a.x * w0.w + a.y * w1.w + a.z * w2.w + a.w * w3.w;
        }
    }

    #pragma unroll
    for (int ii = 0; ii < 8; ii++) {
        int node = base + 8 * ty + ii;
        if (node < nN) {
            float4 o;
            o.x = fmaxf(acc[ii][0] + bfv.x, 0.f);
            o.y = fmaxf(acc[ii][1] + bfv.y, 0.f);
            o.z = fmaxf(acc[ii][2] + bfv.z, 0.f);
            o.w = fmaxf(acc[ii][3] + bfv.w, 0.f);
            *(float4*)(out + (size_t)node * 64 + 4 * tx) = o;
        }
    }
}

// ---------------------------------------------------------------------------
extern "C" void kernel_launch(void* const* d_in, const int* in_sizes, int n_in,
                              void* d_out, int out_size)
{
    const float* x   = (const float*)d_in[0];
    const int*   eit = (const int*)d_in[1];
    const int*   eig = (const int*)d_in[2];
    const float* Wt1 = (const float*)d_in[3];
    const float* bt1 = (const float*)d_in[4];
    const float* Wt2 = (const float*)d_in[5];
    const float* bt2 = (const float*)d_in[6];
    const float* Wg1 = (const float*)d_in[7];
    const float* bg1 = (const float*)d_in[8];
    const float* Wg2 = (const float*)d_in[9];
    const float* bg2 = (const float*)d_in[10];
    const float* Wf  = (const float*)d_in[11];
    const float* bf  = (const float*)d_in[12];
    float* out = (float*)d_out;

    const int nN = in_sizes[0] / 64;
    const int nE = in_sizes[1] / 2;

    void* poolPtr = nullptr;
    cudaGetSymbolAddress(&poolPtr, g_pool);
    cudaMemsetAsync(poolPtr, 0, sizeof(float) * 2 * (size_t)N_MAX * 64, 0);

    const int smemN = (64 * 260 + 128 * 68) * 4;
    cudaFuncSetAttribute(node_kernel,
                         cudaFuncAttributeMaxDynamicSharedMemorySize, smemN);
    node_kernel<<<(nN + 127) / 128, 512, smemN>>>(x, Wt1, Wg1, bt1, bg1, nN);

    dim3 gridB(222, 2);
    branch_kernel<<<gridB, 256>>>(eit, eig, Wt2, Wg2, bt2, bg2, nE);

    const int smemF = (128 * 64 + 128 * 132) * 4;
    cudaFuncSetAttribute(final_kernel,
                         cudaFuncAttributeMaxDynamicSharedMemorySize, smemF);
    final_kernel<<<(nN + 127) / 128, 256, smemF>>>(Wf, bf, out, nN);
}